// round 10
// baseline (speedup 1.0000x reference)
#include <cuda_runtime.h>
#include <math.h>
#include <stdio.h>

#define NATOMS 10000
#define NEDGES 64000
#define NB     128
#define NH     600
#define NG     50
#define NL     6
#define LOG2F_C 0.6931471805599453f
#define PI_F    3.14159265358979323846f

// ---------------- scratch (device globals; no allocation allowed) ----------------
__device__ float g_rbf [(size_t)NEDGES * NG];
__device__ float g_Ccut[NEDGES];
__device__ float g_h   [(size_t)NATOMS * NH];
__device__ float g_t1  [(size_t)NEDGES * NH];
__device__ float g_W   [(size_t)NEDGES * NH];
__device__ float g_hp  [(size_t)NATOMS * NH];
__device__ float g_agg [(size_t)NATOMS * NH];
__device__ float g_x   [(size_t)NATOMS * NH];
__device__ float g_pool[(size_t)NB * NH];
__device__ float g_cnt [NB];

__device__ __forceinline__ float ssp(float x) {
    return log1pf(expf(-fabsf(x))) + fmaxf(x, 0.0f) - LOG2F_C;
}

__device__ __forceinline__ float f2tf(float x) {
    unsigned r;
    asm("cvt.rna.tf32.f32 %0, %1;" : "=r"(r) : "f"(x));
    return __uint_as_float(r);
}

__device__ __forceinline__ void mma_tf32(float* c, const float4 a, const float2 b) {
    asm volatile(
        "mma.sync.aligned.m16n8k8.row.col.f32.tf32.tf32.f32 "
        "{%0,%1,%2,%3}, {%4,%5,%6,%7}, {%8,%9}, {%0,%1,%2,%3};\n"
        : "+f"(c[0]), "+f"(c[1]), "+f"(c[2]), "+f"(c[3])
        : "r"(__float_as_uint(a.x)), "r"(__float_as_uint(a.y)),
          "r"(__float_as_uint(a.z)), "r"(__float_as_uint(a.w)),
          "r"(__float_as_uint(b.x)), "r"(__float_as_uint(b.y)));
}

// ---------------- edge geometry ----------------
__global__ void edge_geom_kernel(const float* __restrict__ pos,
                                 const int* __restrict__ ei,
                                 float* __restrict__ rbf,
                                 float* __restrict__ Ccut) {
    int e = blockIdx.x * blockDim.x + threadIdx.x;
    if (e >= NEDGES) return;
    int s = ei[e];
    int t = ei[NEDGES + e];
    float dx = pos[3*s+0] - pos[3*t+0];
    float dy = pos[3*s+1] - pos[3*t+1];
    float dz = pos[3*s+2] - pos[3*t+2];
    float d = sqrtf(dx*dx + dy*dy + dz*dz + 1e-12f);
    Ccut[e] = 0.5f * (cosf(d * (PI_F / 10.0f)) + 1.0f);
    const float delta = 10.0f / 49.0f;
    const float coeff = -0.5f / (delta * delta);
    #pragma unroll
    for (int g = 0; g < NG; g++) {
        float u = d - (float)g * delta;
        rbf[(size_t)e * NG + g] = expf(coeff * u * u);
    }
}

// ---------------- h init ----------------
__global__ void init_h_kernel(const int* __restrict__ z,
                              const float* __restrict__ emb,
                              float* __restrict__ h) {
    size_t idx = (size_t)blockIdx.x * blockDim.x + threadIdx.x;
    if (idx >= (size_t)NATOMS * NH) return;
    int n = (int)(idx / NH);
    int c = (int)(idx - (size_t)n * NH);
    h[idx] = emb[(size_t)z[n] * NH + c];
}

// ---------------- TF32 tensor-core GEMM, fragment-native smem layout ----------
// C[M,N] = A[M,K] @ B[K,N], row-major. 128x128x16 CTA tile, 8 warps, 64x32 warp tile.
// Smem holds MMA fragments directly:
//  A: 16 chunks (a=0..7 x kc=0..1), chunk = 32 lanes x float4 (slot order a0,a1,a2,a3),
//     padded pitch 132 floats. Element (mr,kr): lane=(mr&7)*4+(kr&3), slot=(mr>>3)+2*(kr>>2).
//  B: 16 chunks (nb=0..15), chunk = 32 lanes x float4 (slots: kk0{b0,b1}, kk1{b0,b1}),
//     padded pitch 132. Element (kr,nr,kc): lane=nr*4+(kr&3), slot=(kr>>2)+2*kc.
// Fragment fetch = 1 LDS.128 per fragment, conflict-free.
// EPI 0: out=v+bias  1: out=ssp(v+bias)  2: out=(v+bias)*rowmul[row]  3: out=v
// EPI 4: acc[row,col] += v+bias  (residual)
#define CHP 132

template<int EPI>
__global__ __launch_bounds__(256, 2)
void gemm_tc(const float* __restrict__ A, const float* __restrict__ Bm,
             const float* __restrict__ bias, float* __restrict__ Cout,
             int M, int Nn, int K,
             const float* __restrict__ rowmul, float* __restrict__ accp)
{
    __shared__ float Af[16 * CHP];
    __shared__ float Bf[16 * CHP];

    const int tid  = threadIdx.x;
    const int lane = tid & 31;
    const int warp = tid >> 5;
    const int wm = (warp >> 2) * 64;   // 0/64
    const int wn = (warp &  3) * 32;   // 0/32/64/96
    const int g = lane >> 2;
    const int t = lane & 3;
    const int m0 = blockIdx.y * 128;
    const int n0 = blockIdx.x * 128;

    // staging indices (computed once)
    const int amI[2] = { (tid + 0)   >> 2, (tid + 256) >> 2 };        // m: 0..127
    const int at4[2] = { ((tid + 0) & 3) << 2, ((tid + 256) & 3) << 2 };
    const int bkI[2] = { (tid + 0)   >> 5, (tid + 256) >> 5 };        // k: 0..15
    const int bn4[2] = { ((tid + 0) & 31) << 2, ((tid + 256) & 31) << 2 };

    float acc[4][4][4];
    #pragma unroll
    for (int i = 0; i < 4; i++)
        #pragma unroll
        for (int j = 0; j < 4; j++)
            #pragma unroll
            for (int r = 0; r < 4; r++) acc[i][j][r] = 0.0f;

    const bool kvec = ((K & 3) == 0);
    float4 aReg[2], bReg[2];

    auto loadTile = [&](int kt) {
        #pragma unroll
        for (int i = 0; i < 2; i++) {
            int row = m0 + amI[i], col = kt + at4[i];
            float4 v = make_float4(0.f, 0.f, 0.f, 0.f);
            if (row < M) {
                if (kvec && col + 4 <= K) {
                    v = *(const float4*)&A[(size_t)row * K + col];
                } else {
                    const float* ap = &A[(size_t)row * K];
                    if (col + 0 < K) v.x = ap[col + 0];
                    if (col + 1 < K) v.y = ap[col + 1];
                    if (col + 2 < K) v.z = ap[col + 2];
                    if (col + 3 < K) v.w = ap[col + 3];
                }
            }
            aReg[i] = v;
            int brow = kt + bkI[i], bcol = n0 + bn4[i];
            float4 w = make_float4(0.f, 0.f, 0.f, 0.f);
            if (brow < K) {
                if (bcol + 4 <= Nn) {
                    w = *(const float4*)&Bm[(size_t)brow * Nn + bcol];
                } else {
                    const float* bp = &Bm[(size_t)brow * Nn];
                    if (bcol + 0 < Nn) w.x = bp[bcol + 0];
                    if (bcol + 1 < Nn) w.y = bp[bcol + 1];
                    if (bcol + 2 < Nn) w.z = bp[bcol + 2];
                    if (bcol + 3 < Nn) w.w = bp[bcol + 3];
                }
            }
            bReg[i] = w;
        }
    };

    auto commitTile = [&]() {
        #pragma unroll
        for (int i = 0; i < 2; i++) {
            // A: element (m, t4+j) -> chunk (a*2+kc), lane=(mr&7)*4+j, slot
            int m = amI[i], t4 = at4[i];
            int a = m >> 4, mr = m & 15;
            int kc = t4 >> 3;
            int slot = (mr >> 3) + ((t4 & 4) >> 1);
            float* dst = &Af[(a * 2 + kc) * CHP + ((mr & 7) << 2) * 4 + slot];
            float fv[4] = {aReg[i].x, aReg[i].y, aReg[i].z, aReg[i].w};
            #pragma unroll
            for (int j = 0; j < 4; j++) dst[j * 4] = f2tf(fv[j]);
            // B: element (k, n4+j)
            int k = bkI[i], n4 = bn4[i];
            int kr = k & 7, bkc = k >> 3;
            int nb = n4 >> 3, nr0 = n4 & 7;
            int bslot = (kr >> 2) + (bkc << 1);
            float* bdst = &Bf[nb * CHP + (nr0 * 4 + (kr & 3)) * 4 + bslot];
            float fw[4] = {bReg[i].x, bReg[i].y, bReg[i].z, bReg[i].w};
            #pragma unroll
            for (int j = 0; j < 4; j++) bdst[j * 16] = f2tf(fw[j]);
        }
    };

    // fragment base addresses (loop-invariant)
    const float* aFragBase = &Af[lane * 4];        // + chunk*CHP
    const float* bFragBase = &Bf[lane * 4];        // + nb*CHP
    const int aT = wm >> 4;                        // 0 or 4: first a-tile of warp
    const int nbT = wn >> 3;                       // 0/4/8/12: first nb of warp

    loadTile(0);

    for (int k0 = 0; k0 < K; k0 += 16) {
        commitTile();
        __syncthreads();

        int kn = k0 + 16;
        if (kn < K) loadTile(kn);

        // B fragments: one LDS.128 per nf covers both kk-steps
        float4 bq[4];
        #pragma unroll
        for (int nf = 0; nf < 4; nf++)
            bq[nf] = *(const float4*)(bFragBase + (nbT + nf) * CHP);

        #pragma unroll
        for (int kc = 0; kc < 2; kc++) {
            float4 aq[4];
            #pragma unroll
            for (int mf = 0; mf < 4; mf++)
                aq[mf] = *(const float4*)(aFragBase + ((aT + mf) * 2 + kc) * CHP);
            #pragma unroll
            for (int mf = 0; mf < 4; mf++)
                #pragma unroll
                for (int nf = 0; nf < 4; nf++) {
                    float2 bb = (kc == 0) ? make_float2(bq[nf].x, bq[nf].y)
                                          : make_float2(bq[nf].z, bq[nf].w);
                    mma_tf32(acc[mf][nf], aq[mf], bb);
                }
        }
        __syncthreads();
    }

    // epilogue
    #pragma unroll
    for (int mf = 0; mf < 4; mf++) {
        #pragma unroll
        for (int nf = 0; nf < 4; nf++) {
            int rb = m0 + wm + mf * 16 + g;
            int cb = n0 + wn + nf * 8 + 2 * t;
            #pragma unroll
            for (int half = 0; half < 2; half++) {
                int mm = rb + half * 8;
                if (mm >= M) continue;
                float v0 = acc[mf][nf][half * 2 + 0];
                float v1 = acc[mf][nf][half * 2 + 1];
                float cm = (EPI == 2) ? rowmul[mm] : 0.0f;
                #pragma unroll
                for (int q = 0; q < 2; q++) {
                    int nn = cb + q;
                    if (nn >= Nn) continue;
                    float v = (q == 0) ? v0 : v1;
                    if (EPI == 0)      { v += bias[nn]; }
                    else if (EPI == 1) { v = ssp(v + bias[nn]); }
                    else if (EPI == 2) { v = (v + bias[nn]) * cm; }
                    else if (EPI == 4) { accp[(size_t)mm * Nn + nn] += v + bias[nn]; continue; }
                    Cout[(size_t)mm * Nn + nn] = v;
                }
            }
        }
    }
}

// ---------------- CFConv scatter (float4 vectorized) ----------------
// NH = 600 = 150 float4 per edge row.
__global__ void scatter_kernel(const int* __restrict__ ei,
                               const float* __restrict__ hp,
                               const float* __restrict__ W,
                               float* __restrict__ agg) {
    size_t idx = (size_t)blockIdx.x * blockDim.x + threadIdx.x;
    const int Q = NH / 4;  // 150
    if (idx >= (size_t)NEDGES * Q) return;
    int e = (int)(idx / Q);
    int c4 = (int)(idx - (size_t)e * Q) * 4;
    int s = ei[e];
    int t = ei[NEDGES + e];
    float4 hv = *(const float4*)&hp[(size_t)s * NH + c4];
    float4 wv = *(const float4*)&W[(size_t)e * NH + c4];
    float* dst = &agg[(size_t)t * NH + c4];
    atomicAdd(dst + 0, hv.x * wv.x);
    atomicAdd(dst + 1, hv.y * wv.y);
    atomicAdd(dst + 2, hv.z * wv.z);
    atomicAdd(dst + 3, hv.w * wv.w);
}

// ---------------- pooling ----------------
__global__ void pool_sum_kernel(const int* __restrict__ batch,
                                const float* __restrict__ h,
                                float* __restrict__ psum) {
    size_t idx = (size_t)blockIdx.x * blockDim.x + threadIdx.x;
    const int Q = NH / 4;
    if (idx >= (size_t)NATOMS * Q) return;
    int n = (int)(idx / Q);
    int c4 = (int)(idx - (size_t)n * Q) * 4;
    float4 hv = *(const float4*)&h[(size_t)n * NH + c4];
    float* dst = &psum[(size_t)batch[n] * NH + c4];
    atomicAdd(dst + 0, hv.x);
    atomicAdd(dst + 1, hv.y);
    atomicAdd(dst + 2, hv.z);
    atomicAdd(dst + 3, hv.w);
}

__global__ void pool_cnt_kernel(const int* __restrict__ batch, float* __restrict__ cnt) {
    int n = blockIdx.x * blockDim.x + threadIdx.x;
    if (n >= NATOMS) return;
    atomicAdd(&cnt[batch[n]], 1.0f);
}

__global__ void pool_div_kernel(float* __restrict__ psum, const float* __restrict__ cnt) {
    int idx = blockIdx.x * blockDim.x + threadIdx.x;
    if (idx >= NB * NH) return;
    int b = idx / NH;
    psum[idx] /= fmaxf(cnt[b], 1.0f);
}

// ---------------- host launcher ----------------
extern "C" void kernel_launch(void* const* d_in, const int* in_sizes, int n_in,
                              void* d_out, int out_size) {
    const int*   z        = (const int*)  d_in[0];
    const float* pos      = (const float*)d_in[1];
    const int*   batch    = (const int*)  d_in[2];
    const int*   ei       = (const int*)  d_in[3];
    const float* emb      = (const float*)d_in[4];
    const float* mlp_w1   = (const float*)d_in[5];
    const float* mlp_b1   = (const float*)d_in[6];
    const float* mlp_w2   = (const float*)d_in[7];
    const float* mlp_b2   = (const float*)d_in[8];
    const float* lin1_w   = (const float*)d_in[9];
    const float* lin2_w   = (const float*)d_in[10];
    const float* lin2_b   = (const float*)d_in[11];
    const float* int_lin_w = (const float*)d_in[12];
    const float* int_lin_b = (const float*)d_in[13];
    const float* pool_w   = (const float*)d_in[14];
    const float* pool_b   = (const float*)d_in[15];
    float* out = (float*)d_out;

    float *p_rbf, *p_C, *p_h, *p_t1, *p_W, *p_hp, *p_agg, *p_x, *p_pool, *p_cnt;
    cudaGetSymbolAddress((void**)&p_rbf,  g_rbf);
    cudaGetSymbolAddress((void**)&p_C,    g_Ccut);
    cudaGetSymbolAddress((void**)&p_h,    g_h);
    cudaGetSymbolAddress((void**)&p_t1,   g_t1);
    cudaGetSymbolAddress((void**)&p_W,    g_W);
    cudaGetSymbolAddress((void**)&p_hp,   g_hp);
    cudaGetSymbolAddress((void**)&p_agg,  g_agg);
    cudaGetSymbolAddress((void**)&p_x,    g_x);
    cudaGetSymbolAddress((void**)&p_pool, g_pool);
    cudaGetSymbolAddress((void**)&p_cnt,  g_cnt);

    edge_geom_kernel<<<(NEDGES + 255) / 256, 256>>>(pos, ei, p_rbf, p_C);
    {
        size_t tot = (size_t)NATOMS * NH;
        init_h_kernel<<<(unsigned)((tot + 255) / 256), 256>>>(z, emb, p_h);
    }

    dim3 blk(256);
    dim3 gE((NH + 127) / 128, (NEDGES + 127) / 128);
    dim3 gN((NH + 127) / 128, (NATOMS + 127) / 128);
    dim3 gB((NH + 127) / 128, (NB + 127) / 128);

    for (int k = 0; k < NL; k++) {
        const float* w1  = mlp_w1 + (size_t)k * NG * NH;
        const float* b1  = mlp_b1 + (size_t)k * NH;
        const float* w2  = mlp_w2 + (size_t)k * NH * NH;
        const float* b2  = mlp_b2 + (size_t)k * NH;
        const float* l1  = lin1_w + (size_t)k * NH * NH;
        const float* l2  = lin2_w + (size_t)k * NH * NH;
        const float* l2b = lin2_b + (size_t)k * NH;
        const float* il  = int_lin_w + (size_t)k * NH * NH;
        const float* ilb = int_lin_b + (size_t)k * NH;

        // t1 = ssp(rbf @ w1 + b1)           [E,H]
        gemm_tc<1><<<gE, blk>>>(p_rbf, w1, b1, p_t1, NEDGES, NH, NG, nullptr, nullptr);
        // W = (t1 @ w2 + b2) * C[:,None]    [E,H]
        gemm_tc<2><<<gE, blk>>>(p_t1, w2, b2, p_W, NEDGES, NH, NH, p_C, nullptr);
        // hp = h @ lin1                     [N,H]
        gemm_tc<3><<<gN, blk>>>(p_h, l1, nullptr, p_hp, NATOMS, NH, NH, nullptr, nullptr);
        // agg = scatter_add(hp[src] * W, dst)
        cudaMemsetAsync(p_agg, 0, (size_t)NATOMS * NH * sizeof(float));
        {
            size_t tot = (size_t)NEDGES * (NH / 4);
            scatter_kernel<<<(unsigned)((tot + 255) / 256), 256>>>(ei, p_hp, p_W, p_agg);
        }
        // x = ssp(agg @ lin2 + lin2_b)      [N,H]
        gemm_tc<1><<<gN, blk>>>(p_agg, l2, l2b, p_x, NATOMS, NH, NH, nullptr, nullptr);
        // h += x @ int_lin + int_lin_b      [N,H]
        gemm_tc<4><<<gN, blk>>>(p_x, il, ilb, nullptr, NATOMS, NH, NH, nullptr, p_h);
    }

    cudaMemsetAsync(p_pool, 0, (size_t)NB * NH * sizeof(float));
    cudaMemsetAsync(p_cnt, 0, NB * sizeof(float));
    {
        size_t tot = (size_t)NATOMS * (NH / 4);
        pool_sum_kernel<<<(unsigned)((tot + 255) / 256), 256>>>(batch, p_h, p_pool);
    }
    pool_cnt_kernel<<<(NATOMS + 255) / 256, 256>>>(batch, p_cnt);
    pool_div_kernel<<<(NB * NH + 255) / 256, 256>>>(p_pool, p_cnt);

    // out = pooled @ pool_w + pool_b       [B,H]
    gemm_tc<0><<<gB, blk>>>(p_pool, pool_w, pool_b, out, NB, NH, NH, nullptr, nullptr);
}

// round 11
// speedup vs baseline: 1.1619x; 1.1619x over previous
#include <cuda_runtime.h>
#include <math.h>
#include <stdio.h>

#define NATOMS 10000
#define NEDGES 64000
#define NB     128
#define NH     600
#define NG     50
#define NL     6
#define LOG2F_C 0.6931471805599453f
#define PI_F    3.14159265358979323846f

// ---------------- scratch (device globals; no allocation allowed) ----------------
__device__ float g_rbf [(size_t)NEDGES * NG];
__device__ float g_Ccut[NEDGES];
__device__ float g_h   [(size_t)NATOMS * NH];
__device__ float g_t1  [(size_t)NEDGES * NH];
__device__ float g_W   [(size_t)NEDGES * NH];
__device__ float g_hp  [(size_t)NATOMS * NH];
__device__ float g_agg [(size_t)NATOMS * NH];
__device__ float g_x   [(size_t)NATOMS * NH];
__device__ float g_pool[(size_t)NB * NH];
__device__ float g_cnt [NB];

__device__ __forceinline__ float ssp(float x) {
    return log1pf(expf(-fabsf(x))) + fmaxf(x, 0.0f) - LOG2F_C;
}

__device__ __forceinline__ float f2tf(float x) {
    unsigned r;
    asm("cvt.rna.tf32.f32 %0, %1;" : "=r"(r) : "f"(x));
    return __uint_as_float(r);
}

__device__ __forceinline__ void mma_tf32(float* c, const unsigned* a, const unsigned* b) {
    asm volatile(
        "mma.sync.aligned.m16n8k8.row.col.f32.tf32.tf32.f32 "
        "{%0,%1,%2,%3}, {%4,%5,%6,%7}, {%8,%9}, {%0,%1,%2,%3};\n"
        : "+f"(c[0]), "+f"(c[1]), "+f"(c[2]), "+f"(c[3])
        : "r"(a[0]), "r"(a[1]), "r"(a[2]), "r"(a[3]), "r"(b[0]), "r"(b[1]));
}

__device__ __forceinline__ void ldm_x4(unsigned* r, unsigned addr) {
    asm volatile("ldmatrix.sync.aligned.m8n8.x4.shared.b16 {%0,%1,%2,%3}, [%4];"
                 : "=r"(r[0]), "=r"(r[1]), "=r"(r[2]), "=r"(r[3]) : "r"(addr));
}

// ---------------- edge geometry ----------------
__global__ void edge_geom_kernel(const float* __restrict__ pos,
                                 const int* __restrict__ ei,
                                 float* __restrict__ rbf,
                                 float* __restrict__ Ccut) {
    int e = blockIdx.x * blockDim.x + threadIdx.x;
    if (e >= NEDGES) return;
    int s = ei[e];
    int t = ei[NEDGES + e];
    float dx = pos[3*s+0] - pos[3*t+0];
    float dy = pos[3*s+1] - pos[3*t+1];
    float dz = pos[3*s+2] - pos[3*t+2];
    float d = sqrtf(dx*dx + dy*dy + dz*dz + 1e-12f);
    Ccut[e] = 0.5f * (cosf(d * (PI_F / 10.0f)) + 1.0f);
    const float delta = 10.0f / 49.0f;
    const float coeff = -0.5f / (delta * delta);
    #pragma unroll
    for (int g = 0; g < NG; g++) {
        float u = d - (float)g * delta;
        rbf[(size_t)e * NG + g] = expf(coeff * u * u);
    }
}

// ---------------- h init ----------------
__global__ void init_h_kernel(const int* __restrict__ z,
                              const float* __restrict__ emb,
                              float* __restrict__ h) {
    size_t idx = (size_t)blockIdx.x * blockDim.x + threadIdx.x;
    if (idx >= (size_t)NATOMS * NH) return;
    int n = (int)(idx / NH);
    int c = (int)(idx - (size_t)n * NH);
    h[idx] = emb[(size_t)z[n] * NH + c];
}

// ---------------- TF32 tensor-core GEMM, 128x128x16 tile, ldmatrix A ---------
// C[M,N] = A[M,K] @ B[K,N], row-major.
// As: [m][k] pitch 20, A fragments fetched via ldmatrix.m8n8.x4 (conflict-free).
// Bs: [k][n] pitch 136, B fragments scalar LDS (conflict-free).
// EPI 0: out=v+bias  1: out=ssp(v+bias)  2: out=(v+bias)*rowmul[row]  3: out=v
// EPI 4: acc[row,col] += v+bias  (residual)
#define LDA_S 20
#define LDB_S 136

template<int EPI>
__global__ __launch_bounds__(256, 2)
void gemm_tc(const float* __restrict__ A, const float* __restrict__ Bm,
             const float* __restrict__ bias, float* __restrict__ Cout,
             int M, int Nn, int K,
             const float* __restrict__ rowmul, float* __restrict__ accp)
{
    __shared__ float As[128 * LDA_S];   // [m][k]
    __shared__ float Bs[16 * LDB_S];    // [k][n]

    const int tid  = threadIdx.x;
    const int lane = tid & 31;
    const int warp = tid >> 5;
    const int wm = (warp >> 2) * 64;   // 0/64
    const int wn = (warp &  3) * 32;   // 0/32/64/96
    const int g = lane >> 2;
    const int t = lane & 3;
    const int m0 = blockIdx.y * 128;
    const int n0 = blockIdx.x * 128;

    float acc[4][4][4];
    #pragma unroll
    for (int i = 0; i < 4; i++)
        #pragma unroll
        for (int j = 0; j < 4; j++)
            #pragma unroll
            for (int r = 0; r < 4; r++) acc[i][j][r] = 0.0f;

    const bool kvec = ((K & 3) == 0);
    float4 aReg[2], bReg[2];

    auto loadTile = [&](int kt) {
        #pragma unroll
        for (int i = 0; i < 2; i++) {
            int idx = tid + i * 256;
            int m = idx >> 2, t4 = (idx & 3) << 2;
            int row = m0 + m, col = kt + t4;
            float4 v = make_float4(0.f, 0.f, 0.f, 0.f);
            if (row < M) {
                if (kvec && col + 4 <= K) {
                    v = *(const float4*)&A[(size_t)row * K + col];
                } else {
                    const float* ap = &A[(size_t)row * K];
                    if (col + 0 < K) v.x = ap[col + 0];
                    if (col + 1 < K) v.y = ap[col + 1];
                    if (col + 2 < K) v.z = ap[col + 2];
                    if (col + 3 < K) v.w = ap[col + 3];
                }
            }
            aReg[i] = v;
            int k = idx >> 5, n4 = (idx & 31) << 2;
            int brow = kt + k, bcol = n0 + n4;
            float4 w = make_float4(0.f, 0.f, 0.f, 0.f);
            if (brow < K) {
                if (bcol + 4 <= Nn) {
                    w = *(const float4*)&Bm[(size_t)brow * Nn + bcol];
                } else {
                    const float* bp = &Bm[(size_t)brow * Nn];
                    if (bcol + 0 < Nn) w.x = bp[bcol + 0];
                    if (bcol + 1 < Nn) w.y = bp[bcol + 1];
                    if (bcol + 2 < Nn) w.z = bp[bcol + 2];
                    if (bcol + 3 < Nn) w.w = bp[bcol + 3];
                }
            }
            bReg[i] = w;
        }
    };

    auto commitTile = [&]() {
        #pragma unroll
        for (int i = 0; i < 2; i++) {
            int idx = tid + i * 256;
            int m = idx >> 2, t4 = (idx & 3) << 2;
            float4 v = aReg[i];
            v.x = f2tf(v.x); v.y = f2tf(v.y); v.z = f2tf(v.z); v.w = f2tf(v.w);
            *(float4*)&As[m * LDA_S + t4] = v;
            int k = idx >> 5, n4 = (idx & 31) << 2;
            float4 w = bReg[i];
            w.x = f2tf(w.x); w.y = f2tf(w.y); w.z = f2tf(w.z); w.w = f2tf(w.w);
            *(float4*)&Bs[k * LDB_S + n4] = w;
        }
    };

    // per-lane ldmatrix row address for A fragments:
    // matrix j = lane>>3: j0 -> (m 0-7, k 0-3), j1 -> (m 8-15, k 0-3),
    //                     j2 -> (m 0-7, k 4-7), j3 -> (m 8-15, k 4-7)
    const int m_lane = wm + ((lane >> 3) & 1) * 8 + (lane & 7);
    const int k_off  = (lane >> 4) * 4;
    const unsigned aSm = (unsigned)__cvta_generic_to_shared(As);
    const unsigned aLaneAddr = aSm + (unsigned)(m_lane * LDA_S + k_off) * 4u;

    loadTile(0);

    for (int k0 = 0; k0 < K; k0 += 16) {
        commitTile();
        __syncthreads();

        int kn = k0 + 16;
        if (kn < K) loadTile(kn);

        #pragma unroll
        for (int kk = 0; kk < 16; kk += 8) {
            unsigned bf[4][2];
            const float* bRow0 = &Bs[(kk + t)     * LDB_S + wn + g];
            const float* bRow1 = &Bs[(kk + t + 4) * LDB_S + wn + g];
            #pragma unroll
            for (int nf = 0; nf < 4; nf++) {
                bf[nf][0] = __float_as_uint(bRow0[nf * 8]);
                bf[nf][1] = __float_as_uint(bRow1[nf * 8]);
            }
            unsigned af[4][4];
            #pragma unroll
            for (int mf = 0; mf < 4; mf++)
                ldm_x4(af[mf], aLaneAddr + (unsigned)(mf * 16 * LDA_S + kk) * 4u);
            #pragma unroll
            for (int mf = 0; mf < 4; mf++)
                #pragma unroll
                for (int nf = 0; nf < 4; nf++)
                    mma_tf32(acc[mf][nf], af[mf], bf[nf]);
        }
        __syncthreads();
    }

    // epilogue
    #pragma unroll
    for (int mf = 0; mf < 4; mf++) {
        #pragma unroll
        for (int nf = 0; nf < 4; nf++) {
            int rb = m0 + wm + mf * 16 + g;
            int cb = n0 + wn + nf * 8 + 2 * t;
            #pragma unroll
            for (int half = 0; half < 2; half++) {
                int mm = rb + half * 8;
                if (mm >= M) continue;
                float v0 = acc[mf][nf][half * 2 + 0];
                float v1 = acc[mf][nf][half * 2 + 1];
                float cm = (EPI == 2) ? rowmul[mm] : 0.0f;
                #pragma unroll
                for (int q = 0; q < 2; q++) {
                    int nn = cb + q;
                    if (nn >= Nn) continue;
                    float v = (q == 0) ? v0 : v1;
                    if (EPI == 0)      { v += bias[nn]; }
                    else if (EPI == 1) { v = ssp(v + bias[nn]); }
                    else if (EPI == 2) { v = (v + bias[nn]) * cm; }
                    else if (EPI == 4) { accp[(size_t)mm * Nn + nn] += v + bias[nn]; continue; }
                    Cout[(size_t)mm * Nn + nn] = v;
                }
            }
        }
    }
}

// ---------------- CFConv scatter (float4 vectorized) ----------------
__global__ void scatter_kernel(const int* __restrict__ ei,
                               const float* __restrict__ hp,
                               const float* __restrict__ W,
                               float* __restrict__ agg) {
    size_t idx = (size_t)blockIdx.x * blockDim.x + threadIdx.x;
    const int Q = NH / 4;  // 150
    if (idx >= (size_t)NEDGES * Q) return;
    int e = (int)(idx / Q);
    int c4 = (int)(idx - (size_t)e * Q) * 4;
    int s = ei[e];
    int t = ei[NEDGES + e];
    float4 hv = *(const float4*)&hp[(size_t)s * NH + c4];
    float4 wv = *(const float4*)&W[(size_t)e * NH + c4];
    float* dst = &agg[(size_t)t * NH + c4];
    atomicAdd(dst + 0, hv.x * wv.x);
    atomicAdd(dst + 1, hv.y * wv.y);
    atomicAdd(dst + 2, hv.z * wv.z);
    atomicAdd(dst + 3, hv.w * wv.w);
}

// ---------------- pooling ----------------
__global__ void pool_sum_kernel(const int* __restrict__ batch,
                                const float* __restrict__ h,
                                float* __restrict__ psum) {
    size_t idx = (size_t)blockIdx.x * blockDim.x + threadIdx.x;
    const int Q = NH / 4;
    if (idx >= (size_t)NATOMS * Q) return;
    int n = (int)(idx / Q);
    int c4 = (int)(idx - (size_t)n * Q) * 4;
    float4 hv = *(const float4*)&h[(size_t)n * NH + c4];
    float* dst = &psum[(size_t)batch[n] * NH + c4];
    atomicAdd(dst + 0, hv.x);
    atomicAdd(dst + 1, hv.y);
    atomicAdd(dst + 2, hv.z);
    atomicAdd(dst + 3, hv.w);
}

__global__ void pool_cnt_kernel(const int* __restrict__ batch, float* __restrict__ cnt) {
    int n = blockIdx.x * blockDim.x + threadIdx.x;
    if (n >= NATOMS) return;
    atomicAdd(&cnt[batch[n]], 1.0f);
}

__global__ void pool_div_kernel(float* __restrict__ psum, const float* __restrict__ cnt) {
    int idx = blockIdx.x * blockDim.x + threadIdx.x;
    if (idx >= NB * NH) return;
    int b = idx / NH;
    psum[idx] /= fmaxf(cnt[b], 1.0f);
}

// ---------------- host launcher ----------------
extern "C" void kernel_launch(void* const* d_in, const int* in_sizes, int n_in,
                              void* d_out, int out_size) {
    const int*   z        = (const int*)  d_in[0];
    const float* pos      = (const float*)d_in[1];
    const int*   batch    = (const int*)  d_in[2];
    const int*   ei       = (const int*)  d_in[3];
    const float* emb      = (const float*)d_in[4];
    const float* mlp_w1   = (const float*)d_in[5];
    const float* mlp_b1   = (const float*)d_in[6];
    const float* mlp_w2   = (const float*)d_in[7];
    const float* mlp_b2   = (const float*)d_in[8];
    const float* lin1_w   = (const float*)d_in[9];
    const float* lin2_w   = (const float*)d_in[10];
    const float* lin2_b   = (const float*)d_in[11];
    const float* int_lin_w = (const float*)d_in[12];
    const float* int_lin_b = (const float*)d_in[13];
    const float* pool_w   = (const float*)d_in[14];
    const float* pool_b   = (const float*)d_in[15];
    float* out = (float*)d_out;

    float *p_rbf, *p_C, *p_h, *p_t1, *p_W, *p_hp, *p_agg, *p_x, *p_pool, *p_cnt;
    cudaGetSymbolAddress((void**)&p_rbf,  g_rbf);
    cudaGetSymbolAddress((void**)&p_C,    g_Ccut);
    cudaGetSymbolAddress((void**)&p_h,    g_h);
    cudaGetSymbolAddress((void**)&p_t1,   g_t1);
    cudaGetSymbolAddress((void**)&p_W,    g_W);
    cudaGetSymbolAddress((void**)&p_hp,   g_hp);
    cudaGetSymbolAddress((void**)&p_agg,  g_agg);
    cudaGetSymbolAddress((void**)&p_x,    g_x);
    cudaGetSymbolAddress((void**)&p_pool, g_pool);
    cudaGetSymbolAddress((void**)&p_cnt,  g_cnt);

    edge_geom_kernel<<<(NEDGES + 255) / 256, 256>>>(pos, ei, p_rbf, p_C);
    {
        size_t tot = (size_t)NATOMS * NH;
        init_h_kernel<<<(unsigned)((tot + 255) / 256), 256>>>(z, emb, p_h);
    }

    dim3 blk(256);
    dim3 gE((NH + 127) / 128, (NEDGES + 127) / 128);
    dim3 gN((NH + 127) / 128, (NATOMS + 127) / 128);
    dim3 gB((NH + 127) / 128, (NB + 127) / 128);

    for (int k = 0; k < NL; k++) {
        const float* w1  = mlp_w1 + (size_t)k * NG * NH;
        const float* b1  = mlp_b1 + (size_t)k * NH;
        const float* w2  = mlp_w2 + (size_t)k * NH * NH;
        const float* b2  = mlp_b2 + (size_t)k * NH;
        const float* l1  = lin1_w + (size_t)k * NH * NH;
        const float* l2  = lin2_w + (size_t)k * NH * NH;
        const float* l2b = lin2_b + (size_t)k * NH;
        const float* il  = int_lin_w + (size_t)k * NH * NH;
        const float* ilb = int_lin_b + (size_t)k * NH;

        // t1 = ssp(rbf @ w1 + b1)           [E,H]
        gemm_tc<1><<<gE, blk>>>(p_rbf, w1, b1, p_t1, NEDGES, NH, NG, nullptr, nullptr);
        // W = (t1 @ w2 + b2) * C[:,None]    [E,H]
        gemm_tc<2><<<gE, blk>>>(p_t1, w2, b2, p_W, NEDGES, NH, NH, p_C, nullptr);
        // hp = h @ lin1                     [N,H]
        gemm_tc<3><<<gN, blk>>>(p_h, l1, nullptr, p_hp, NATOMS, NH, NH, nullptr, nullptr);
        // agg = scatter_add(hp[src] * W, dst)
        cudaMemsetAsync(p_agg, 0, (size_t)NATOMS * NH * sizeof(float));
        {
            size_t tot = (size_t)NEDGES * (NH / 4);
            scatter_kernel<<<(unsigned)((tot + 255) / 256), 256>>>(ei, p_hp, p_W, p_agg);
        }
        // x = ssp(agg @ lin2 + lin2_b)      [N,H]
        gemm_tc<1><<<gN, blk>>>(p_agg, l2, l2b, p_x, NATOMS, NH, NH, nullptr, nullptr);
        // h += x @ int_lin + int_lin_b      [N,H]
        gemm_tc<4><<<gN, blk>>>(p_x, il, ilb, nullptr, NATOMS, NH, NH, nullptr, p_h);
    }

    cudaMemsetAsync(p_pool, 0, (size_t)NB * NH * sizeof(float));
    cudaMemsetAsync(p_cnt, 0, NB * sizeof(float));
    {
        size_t tot = (size_t)NATOMS * (NH / 4);
        pool_sum_kernel<<<(unsigned)((tot + 255) / 256), 256>>>(batch, p_h, p_pool);
    }
    pool_cnt_kernel<<<(NATOMS + 255) / 256, 256>>>(batch, p_cnt);
    pool_div_kernel<<<(NB * NH + 255) / 256, 256>>>(p_pool, p_cnt);

    // out = pooled @ pool_w + pool_b       [B,H]
    gemm_tc<0><<<gB, blk>>>(p_pool, pool_w, pool_b, out, NB, NH, NH, nullptr, nullptr);
}